// round 3
// baseline (speedup 1.0000x reference)
#include <cuda_runtime.h>
#include <math.h>

// ---------------- problem constants ----------------
#define Lq   4          // sequence length (B=1)
#define Cc   128        // channels
#define Ch   64         // hidden = C/2
#define Rr   8          // rank
#define Kk   36         // Lmax^2
#define HW   115200     // 240*480 pixels per plane
#define WFN  (Cc*Rr + Rr*Kk)   // 1312 hypernet output width

// ---------------- device scratch ----------------
__device__ float g_ctx[Lq * Cc];
__device__ float g_gW1[Lq * Cc * Rr];     // gain[c]*W1[l,c,r]
__device__ float g_W2 [Lq * Rr * Kk];     // W2[l,r,k]

// ---------------- f32x2 helpers (sm_103a packed fp32) ----------------
__device__ __forceinline__ void fma2(unsigned long long& d,
                                     unsigned long long a,
                                     unsigned long long b) {
    asm("fma.rn.f32x2 %0, %1, %2, %0;" : "+l"(d) : "l"(a), "l"(b));
}
__device__ __forceinline__ unsigned long long pack2(float w) {
    unsigned long long p;
    asm("mov.b64 %0, {%1, %1};" : "=l"(p) : "f"(w));
    return p;
}

// ============================================================
// Kernel 1: per-(l,c) plane mean of x  -> g_ctx
// grid = 512, 256 threads; 4-way batched loads (MLP_p1 = 4)
// ============================================================
__global__ void mean_kernel(const float* __restrict__ x)
{
    const int plane = blockIdx.x;
    const float4* __restrict__ p = (const float4*)(x + (size_t)plane * HW);
    const int n4 = HW / 4;                        // 28800

    float s0 = 0.f, s1 = 0.f, s2 = 0.f, s3 = 0.f;
    int i = threadIdx.x;
    for (; i + 768 < n4; i += 1024) {
        float4 a = p[i];
        float4 b = p[i + 256];
        float4 c = p[i + 512];
        float4 d = p[i + 768];
        s0 += (a.x + a.y) + (a.z + a.w);
        s1 += (b.x + b.y) + (b.z + b.w);
        s2 += (c.x + c.y) + (c.z + c.w);
        s3 += (d.x + d.y) + (d.z + d.w);
    }
    for (; i < n4; i += 256) {
        float4 a = p[i];
        s0 += (a.x + a.y) + (a.z + a.w);
    }
    float s = (s0 + s1) + (s2 + s3);

    #pragma unroll
    for (int o = 16; o > 0; o >>= 1)
        s += __shfl_xor_sync(0xffffffffu, s, o);

    __shared__ float ws[8];
    const int lane = threadIdx.x & 31, wid = threadIdx.x >> 5;
    if (lane == 0) ws[wid] = s;
    __syncthreads();
    if (wid == 0) {
        s = (lane < 8) ? ws[lane] : 0.f;
        #pragma unroll
        for (int o = 4; o > 0; o >>= 1)
            s += __shfl_xor_sync(0xffffffffu, s, o);
        if (lane == 0)
            g_ctx[plane] = s * (1.0f / (float)HW);
    }
}

// ============================================================
// Kernel 2: hypernet (tiny).  1 block, 512 threads.
// ============================================================
__global__ void hyper_kernel(const float* __restrict__ Wa,
                             const float* __restrict__ ba,
                             const float* __restrict__ Wb,
                             const float* __restrict__ bb,
                             const float* __restrict__ gain)
{
    __shared__ float hs[Lq * Ch];
    __shared__ float ctxs[Lq * Cc];

    const int tid = threadIdx.x;
    if (tid < Lq * Cc) ctxs[tid] = g_ctx[tid];
    __syncthreads();

    if (tid < Lq * Ch) {
        const int l = tid >> 6;
        const int j = tid & 63;
        float acc = ba[j];
        const float* c = &ctxs[l * Cc];
        #pragma unroll 8
        for (int i = 0; i < Cc; i++)
            acc = fmaf(c[i], Wa[i * Ch + j], acc);
        hs[tid] = acc / (1.0f + expf(-acc));
    }
    __syncthreads();

    for (int idx = tid; idx < Lq * WFN; idx += blockDim.x) {
        const int l   = idx / WFN;
        const int col = idx - l * WFN;
        float acc = bb[col];
        const float* h = &hs[l * Ch];
        #pragma unroll 8
        for (int j = 0; j < Ch; j++)
            acc = fmaf(h[j], Wb[j * WFN + col], acc);
        if (col < Cc * Rr) {
            const int c = col >> 3;
            g_gW1[l * (Cc * Rr) + col] = gain[c] * acc;
        } else {
            g_W2[l * (Rr * Kk) + (col - Cc * Rr)] = acc;
        }
    }
}

// ============================================================
// Kernel 3: fused z = W2@Y + out = x + gW1@z, packed f32x2 math.
// grid = (225, 4), 128 threads, 4 pixels/thread.
// ============================================================
__global__ void __launch_bounds__(128)
bias_kernel(const float* __restrict__ x,
            const float* __restrict__ Y,
            float*       __restrict__ out)
{
    const int l  = blockIdx.y;
    const int p0 = (blockIdx.x * 128 + threadIdx.x) * 4;

    // packed {w,w} weights in shared (16B-aligned for LDS.128)
    __shared__ __align__(16) unsigned long long sW2p[Kk * Rr];  // [k][r], 2.3KB
    __shared__ __align__(16) unsigned long long sW1p[Cc * Rr];  // [c][r], 8KB

    for (int i = threadIdx.x; i < Kk * Rr; i += 128) {
        const int k = i >> 3, r = i & 7;
        sW2p[i] = pack2(g_W2[l * Rr * Kk + r * Kk + k]);
    }
    for (int i = threadIdx.x; i < Cc * Rr; i += 128) {
        sW1p[i] = pack2(g_gW1[l * Cc * Rr + i]);
    }
    __syncthreads();

    // ---- z[r] for pixel pairs {0,1} and {2,3} ----
    unsigned long long z0[Rr], z1[Rr];
    #pragma unroll
    for (int r = 0; r < Rr; r++) { z0[r] = 0ull; z1[r] = 0ull; }

    #pragma unroll
    for (int k = 0; k < Kk; k++) {
        const ulonglong2 y = *(const ulonglong2*)(Y + (size_t)k * HW + p0);
        const ulonglong2* wp = (const ulonglong2*)&sW2p[k * Rr];
        #pragma unroll
        for (int rr = 0; rr < 4; rr++) {
            const ulonglong2 w = wp[rr];
            fma2(z0[2 * rr    ], w.x, y.x);
            fma2(z1[2 * rr    ], w.x, y.y);
            fma2(z0[2 * rr + 1], w.y, y.x);
            fma2(z1[2 * rr + 1], w.y, y.y);
        }
    }

    // ---- out = x + gW1 . z over 128 channels ----
    const float* xb = x   + (size_t)l * Cc * HW + p0;
    float*       ob = out + (size_t)l * Cc * HW + p0;

    #pragma unroll 4
    for (int c = 0; c < Cc; c++) {
        ulonglong2 v = *(const ulonglong2*)(xb + (size_t)c * HW);
        const ulonglong2* wp = (const ulonglong2*)&sW1p[c * Rr];
        #pragma unroll
        for (int rr = 0; rr < 4; rr++) {
            const ulonglong2 w = wp[rr];
            fma2(v.x, w.x, z0[2 * rr    ]);
            fma2(v.y, w.x, z1[2 * rr    ]);
            fma2(v.x, w.y, z0[2 * rr + 1]);
            fma2(v.y, w.y, z1[2 * rr + 1]);
        }
        *(ulonglong2*)(ob + (size_t)c * HW) = v;
    }
}

// ============================================================
extern "C" void kernel_launch(void* const* d_in, const int* in_sizes, int n_in,
                              void* d_out, int out_size)
{
    const float* x    = (const float*)d_in[0];
    const float* Wa   = (const float*)d_in[1];
    const float* ba   = (const float*)d_in[2];
    const float* Wb   = (const float*)d_in[3];
    const float* bb   = (const float*)d_in[4];
    const float* gain = (const float*)d_in[5];
    const float* Y    = (const float*)d_in[6];
    float* out        = (float*)d_out;

    mean_kernel<<<Lq * Cc, 256>>>(x);
    hyper_kernel<<<1, 512>>>(Wa, ba, Wb, bb, gain);
    bias_kernel<<<dim3(225, Lq), 128>>>(x, Y, out);
}